// round 10
// baseline (speedup 1.0000x reference)
#include <cuda_runtime.h>
#include <cuda_fp16.h>

#define R_TOT   16384      // H*W rays
#define KPRIM   32
#define NSTEPS  64
#define DTSTEP  (1.0f/64.0f)

// Packed template: per (k,z,y,x): {half2 r(x,x+1), g(x,x+1), b(x,x+1), a(x,x+1)} = 16B
__device__ uint4 g_tpair[KPRIM * 4096];   // 2 MB, L2-resident

// --- Prologue: pack template [K,4,16,16,16] fp32 -> fp16 corner pairs ---
__global__ void pack_tmpl_kernel(const float* __restrict__ tmpl) {
    int idx = blockIdx.x * blockDim.x + threadIdx.x;
    if (idx >= KPRIM * 4096) return;
    int k = idx >> 12;
    int v = idx & 4095;            // z*256 + y*16 + x
    int x = v & 15;
    int x1 = (x < 15) ? 1 : 0;     // clamp x+1
    const float* b = tmpl + (size_t)k * 4 * 4096;
    __half2 hr = __floats2half2_rn(b[v],           b[v + x1]);
    __half2 hg = __floats2half2_rn(b[4096 + v],    b[4096 + v + x1]);
    __half2 hb = __floats2half2_rn(b[8192 + v],    b[8192 + v + x1]);
    __half2 ha = __floats2half2_rn(b[12288 + v],   b[12288 + v + x1]);
    uint4 q;
    q.x = *(unsigned int*)&hr;
    q.y = *(unsigned int*)&hg;
    q.z = *(unsigned int*)&hb;
    q.w = *(unsigned int*)&ha;
    g_tpair[idx] = q;
}

__device__ __forceinline__ float4 xlerp4(uint4 q, float fx) {
    float2 r = __half22float2(*(__half2*)&q.x);
    float2 g = __half22float2(*(__half2*)&q.y);
    float2 b = __half22float2(*(__half2*)&q.z);
    float2 a = __half22float2(*(__half2*)&q.w);
    return make_float4(fmaf(fx, r.y - r.x, r.x),
                       fmaf(fx, g.y - g.x, g.x),
                       fmaf(fx, b.y - b.x, b.x),
                       fmaf(fx, a.y - a.x, a.x));
}

// --- Main march: warp per ray, lane per prim, step-occupancy-mask loop ---
__global__ void __launch_bounds__(256) march_kernel(
    const float* __restrict__ raypos,
    const float* __restrict__ raydir,
    const float* __restrict__ tminmax,
    const float* __restrict__ primpos,
    const float* __restrict__ primrot,
    const float* __restrict__ primscale,
    float* __restrict__ out)
{
    int gtid = blockIdx.x * blockDim.x + threadIdx.x;
    int ray  = gtid >> 5;
    int lane = threadIdx.x & 31;
    if (ray >= R_TOT) return;

    float rpx = raypos[ray * 3 + 0];
    float rpy = raypos[ray * 3 + 1];
    float rpz = raypos[ray * 3 + 2];
    float rdx = raydir[ray * 3 + 0];
    float rdy = raydir[ray * 3 + 1];
    float rdz = raydir[ray * 3 + 2];
    float tmin = tminmax[ray * 2 + 0];
    float tmax = tminmax[ray * 2 + 1];

    // Affine transform coefficients: y_c(t) = a_c + t * b_c  (per-lane prim)
    float a0, a1, a2, b0, b1, b2;
    {
        float ppx = primpos[lane * 3 + 0];
        float ppy = primpos[lane * 3 + 1];
        float ppz = primpos[lane * 3 + 2];
        float r00 = primrot[lane * 9 + 0], r01 = primrot[lane * 9 + 1], r02 = primrot[lane * 9 + 2];
        float r10 = primrot[lane * 9 + 3], r11 = primrot[lane * 9 + 4], r12 = primrot[lane * 9 + 5];
        float r20 = primrot[lane * 9 + 6], r21 = primrot[lane * 9 + 7], r22 = primrot[lane * 9 + 8];
        float s0 = primscale[lane * 3 + 0];
        float s1 = primscale[lane * 3 + 1];
        float s2 = primscale[lane * 3 + 2];
        float dx = rpx - ppx, dy = rpy - ppy, dz = rpz - ppz;
        a0 = (r00 * dx + r01 * dy + r02 * dz) * s0;
        a1 = (r10 * dx + r11 * dy + r12 * dz) * s1;
        a2 = (r20 * dx + r21 * dy + r22 * dz) * s2;
        b0 = (r00 * rdx + r01 * rdy + r02 * rdz) * s0;
        b1 = (r10 * rdx + r11 * rdy + r12 * rdz) * s1;
        b2 = (r20 * rdx + r21 * rdy + r22 * rdz) * s2;
    }

    // Steps with t = tmin + i*DT < tmax
    int nsteps = (int)ceilf((tmax - tmin) * 64.0f);
    nsteps = min(nsteps, NSTEPS);

    // Per-lane slab interval [te, tx]: |a_c + t b_c| <= 1 for all c
    float te = -1e30f, tx = 1e30f;
    bool nonempty = true;
    {
        #define SLAB(A, B)                                                   \
        {                                                                    \
            if ((B) != 0.0f) {                                               \
                float u = (-1.0f - (A)) / (B);                               \
                float v = ( 1.0f - (A)) / (B);                               \
                te = fmaxf(te, fminf(u, v));                                 \
                tx = fminf(tx, fmaxf(u, v));                                 \
            } else if (fabsf(A) > 1.0f) {                                    \
                nonempty = false;                                            \
            }                                                                \
        }
        SLAB(a0, b0) SLAB(a1, b1) SLAB(a2, b2)
        #undef SLAB
        if (te > tx) nonempty = false;
    }

    // Per-lane step-occupancy mask over widened interval [ie-1, ixb+1]
    unsigned long long m = 0;
    if (nonempty) {
        float fe  = fminf(fmaxf((te - tmin) * 64.0f, -2.0f), 100.0f);
        float fx_ = fminf(fmaxf((tx - tmin) * 64.0f, -2.0f), 100.0f);
        int lo = max((int)floorf(fe) - 1, 0);
        int hi = min((int)ceilf(fx_) + 1, nsteps - 1);
        if (hi >= lo) {   // lo <= hi <= 63 guaranteed
            int len = hi - lo + 1;
            unsigned long long ones = (len >= 64) ? ~0ULL : ((1ULL << len) - 1ULL);
            m = ones << lo;
        }
    }
    // Warp OR-reduce of the mask (integer redux, sm_103-legal)
    unsigned mlo = (unsigned)m, mhi = (unsigned)(m >> 32);
    asm("redux.sync.or.b32 %0, %1, 0xffffffff;" : "=r"(mlo) : "r"(mlo));
    asm("redux.sync.or.b32 %0, %1, 0xffffffff;" : "=r"(mhi) : "r"(mhi));
    unsigned long long mask = ((unsigned long long)mhi << 32) | mlo;

    float rgbx = 0.f, rgby = 0.f, rgbz = 0.f, alpha = 0.f;
    const uint4* __restrict__ T = g_tpair + (lane << 12);

    #pragma unroll 1
    while (mask) {
        int i = __ffsll((long long)mask) - 1;   // ascending step order
        mask &= mask - 1ULL;

        float t  = fmaf((float)i, DTSTEP, tmin);
        float y0 = fmaf(t, b0, a0);
        float y1 = fmaf(t, b1, a1);
        float y2 = fmaf(t, b2, a2);

        float sx = 0.f, sy = 0.f, sz = 0.f, sw = 0.f;
        if (fabsf(y0) <= 1.0f && fabsf(y1) <= 1.0f && fabsf(y2) <= 1.0f) {
            // component 0 -> z index, 1 -> y, 2 -> x ; g in [0,15] when inside
            float gz = (y0 + 1.0f) * 7.5f;
            float gy = (y1 + 1.0f) * 7.5f;
            float gx = (y2 + 1.0f) * 7.5f;
            int iz = min((int)gz, 14);
            int iy = min((int)gy, 14);
            int ixx = min((int)gx, 14);
            float fz = gz - (float)iz;
            float fy = gy - (float)iy;
            float fx = gx - (float)ixx;

            int base = iz * 256 + iy * 16 + ixx;
            uint4 q00 = __ldg(T + base);            // (iz,  iy)
            uint4 q01 = __ldg(T + base + 16);       // (iz,  iy+1)
            uint4 q10 = __ldg(T + base + 256);      // (iz+1,iy)
            uint4 q11 = __ldg(T + base + 272);      // (iz+1,iy+1)

            float4 c00 = xlerp4(q00, fx);
            float4 c01 = xlerp4(q01, fx);
            float4 c10 = xlerp4(q10, fx);
            float4 c11 = xlerp4(q11, fx);

            float d0x = fmaf(fy, c01.x - c00.x, c00.x);
            float d0y = fmaf(fy, c01.y - c00.y, c00.y);
            float d0z = fmaf(fy, c01.z - c00.z, c00.z);
            float d0w = fmaf(fy, c01.w - c00.w, c00.w);
            float d1x = fmaf(fy, c11.x - c10.x, c10.x);
            float d1y = fmaf(fy, c11.y - c10.y, c10.y);
            float d1z = fmaf(fy, c11.z - c10.z, c10.z);
            float d1w = fmaf(fy, c11.w - c10.w, c10.w);

            sx = fmaf(fz, d1x - d0x, d0x);
            sy = fmaf(fz, d1y - d0y, d0y);
            sz = fmaf(fz, d1z - d0z, d0z);
            sw = fmaf(fz, d1w - d0w, d0w);
        }

        // Warp-sum of alpha channel (butterfly; fp32 REDUX not on sm_103)
        #pragma unroll
        for (int off = 16; off; off >>= 1)
            sw += __shfl_xor_sync(0xffffffffu, sw, off);

        float na = fminf(fmaf(sw, DTSTEP, alpha), 1.0f);
        float contrib = na - alpha;         // warp-uniform
        rgbx = fmaf(sx, contrib, rgbx);     // per-lane partial; reduced at the end
        rgby = fmaf(sy, contrib, rgby);
        rgbz = fmaf(sz, contrib, rgbz);
        alpha = na;
        if (alpha >= 1.0f) break;           // saturated: all later contribs 0
    }

    // Final rgb reduction across the warp
    #pragma unroll
    for (int off = 16; off; off >>= 1) {
        rgbx += __shfl_xor_sync(0xffffffffu, rgbx, off);
        rgby += __shfl_xor_sync(0xffffffffu, rgby, off);
        rgbz += __shfl_xor_sync(0xffffffffu, rgbz, off);
    }

    if (lane == 0) {
        // out layout: rayrgb [1,3,H,W] | rayalpha [1,1,H,W] | rayrgba [1,4,H,W]
        out[0 * R_TOT + ray] = rgbx;
        out[1 * R_TOT + ray] = rgby;
        out[2 * R_TOT + ray] = rgbz;
        out[3 * R_TOT + ray] = alpha;
        out[4 * R_TOT + ray] = rgbx;
        out[5 * R_TOT + ray] = rgby;
        out[6 * R_TOT + ray] = rgbz;
        out[7 * R_TOT + ray] = alpha;
    }
}

extern "C" void kernel_launch(void* const* d_in, const int* in_sizes, int n_in,
                              void* d_out, int out_size) {
    const float* raypos    = (const float*)d_in[0];
    const float* raydir    = (const float*)d_in[1];
    const float* tminmax   = (const float*)d_in[2];
    const float* primpos   = (const float*)d_in[3];
    const float* primrot   = (const float*)d_in[4];
    const float* primscale = (const float*)d_in[5];
    const float* tmpl      = (const float*)d_in[6];
    float* out = (float*)d_out;

    pack_tmpl_kernel<<<(KPRIM * 4096 + 255) / 256, 256>>>(tmpl);

    int threads = R_TOT * 32;
    march_kernel<<<threads / 256, 256>>>(raypos, raydir, tminmax,
                                         primpos, primrot, primscale, out);
}

// round 11
// speedup vs baseline: 1.1019x; 1.1019x over previous
#include <cuda_runtime.h>
#include <cuda_fp16.h>

#define R_TOT   16384      // H*W rays
#define KPRIM   32
#define NSTEPS  64
#define DTSTEP  (1.0f/64.0f)

// Packed template: per (k,z,y,x): {h2(r,g)@x, h2(b,a)@x, h2(r,g)@x+1, h2(b,a)@x+1} = 16B
__device__ uint4 g_tpair[KPRIM * 4096];   // 2 MB, L2-resident

// --- Prologue: pack template [K,4,16,16,16] fp32 -> channel-pair half2s ---
__global__ void pack_tmpl_kernel(const float* __restrict__ tmpl) {
    int idx = blockIdx.x * blockDim.x + threadIdx.x;
    if (idx >= KPRIM * 4096) return;
    int k = idx >> 12;
    int v = idx & 4095;            // z*256 + y*16 + x
    int x = v & 15;
    int x1 = (x < 15) ? 1 : 0;     // clamp x+1 (offset)
    const float* b = tmpl + (size_t)k * 4 * 4096;
    int p0 = v, p1 = v + x1;
    __half2 rg0 = __floats2half2_rn(b[p0],          b[4096 + p0]);
    __half2 ba0 = __floats2half2_rn(b[8192 + p0],   b[12288 + p0]);
    __half2 rg1 = __floats2half2_rn(b[p1],          b[4096 + p1]);
    __half2 ba1 = __floats2half2_rn(b[8192 + p1],   b[12288 + p1]);
    uint4 q;
    q.x = *(unsigned int*)&rg0;
    q.y = *(unsigned int*)&ba0;
    q.z = *(unsigned int*)&rg1;
    q.w = *(unsigned int*)&ba1;
    g_tpair[idx] = q;
}

__device__ __forceinline__ void xlerp_h2(uint4 q, __half2 fx2, __half2& rg, __half2& ba) {
    __half2 rg0 = *(__half2*)&q.x;
    __half2 ba0 = *(__half2*)&q.y;
    __half2 rg1 = *(__half2*)&q.z;
    __half2 ba1 = *(__half2*)&q.w;
    rg = __hfma2(fx2, __hsub2(rg1, rg0), rg0);
    ba = __hfma2(fx2, __hsub2(ba1, ba0), ba0);
}

// --- Main march: one warp per ray, one lane per primitive, half2 lerp tree ---
__global__ void __launch_bounds__(256) march_kernel(
    const float* __restrict__ raypos,
    const float* __restrict__ raydir,
    const float* __restrict__ tminmax,
    const float* __restrict__ primpos,
    const float* __restrict__ primrot,
    const float* __restrict__ primscale,
    float* __restrict__ out)
{
    int gtid = blockIdx.x * blockDim.x + threadIdx.x;
    int ray  = gtid >> 5;
    int lane = threadIdx.x & 31;
    if (ray >= R_TOT) return;

    float rpx = raypos[ray * 3 + 0];
    float rpy = raypos[ray * 3 + 1];
    float rpz = raypos[ray * 3 + 2];
    float rdx = raydir[ray * 3 + 0];
    float rdy = raydir[ray * 3 + 1];
    float rdz = raydir[ray * 3 + 2];
    float tmin = tminmax[ray * 2 + 0];
    float tmax = tminmax[ray * 2 + 1];

    // Affine transform coefficients: y_c(t) = a_c + t * b_c  (per-lane prim)
    float a0, a1, a2, b0, b1, b2;
    {
        float ppx = primpos[lane * 3 + 0];
        float ppy = primpos[lane * 3 + 1];
        float ppz = primpos[lane * 3 + 2];
        float r00 = primrot[lane * 9 + 0], r01 = primrot[lane * 9 + 1], r02 = primrot[lane * 9 + 2];
        float r10 = primrot[lane * 9 + 3], r11 = primrot[lane * 9 + 4], r12 = primrot[lane * 9 + 5];
        float r20 = primrot[lane * 9 + 6], r21 = primrot[lane * 9 + 7], r22 = primrot[lane * 9 + 8];
        float s0 = primscale[lane * 3 + 0];
        float s1 = primscale[lane * 3 + 1];
        float s2 = primscale[lane * 3 + 2];
        float dx = rpx - ppx, dy = rpy - ppy, dz = rpz - ppz;
        a0 = (r00 * dx + r01 * dy + r02 * dz) * s0;
        a1 = (r10 * dx + r11 * dy + r12 * dz) * s1;
        a2 = (r20 * dx + r21 * dy + r22 * dz) * s2;
        b0 = (r00 * rdx + r01 * rdy + r02 * rdz) * s0;
        b1 = (r10 * rdx + r11 * rdy + r12 * rdz) * s1;
        b2 = (r20 * rdx + r21 * rdy + r22 * rdz) * s2;
    }

    // Steps with t = tmin + i*DT < tmax
    int nsteps = (int)ceilf((tmax - tmin) * 64.0f);
    nsteps = min(nsteps, NSTEPS);

    // Per-lane slab interval [te, tx]: |a_c + t b_c| <= 1 for all c
    float te = -1e30f, tx = 1e30f;
    bool nonempty = true;
    {
        #define SLAB(A, B)                                                   \
        {                                                                    \
            if ((B) != 0.0f) {                                               \
                float u = (-1.0f - (A)) / (B);                               \
                float v = ( 1.0f - (A)) / (B);                               \
                te = fmaxf(te, fminf(u, v));                                 \
                tx = fminf(tx, fmaxf(u, v));                                 \
            } else if (fabsf(A) > 1.0f) {                                    \
                nonempty = false;                                            \
            }                                                                \
        }
        SLAB(a0, b0) SLAB(a1, b1) SLAB(a2, b2)
        #undef SLAB
        if (te > tx) nonempty = false;
    }

    // Step-index bounds (widened 1 step for rounding safety)
    int ie, ixb;
    if (nonempty) {
        float fe  = fminf(fmaxf((te - tmin) * 64.0f, -2.0f), 100.0f);
        float fx_ = fminf(fmaxf((tx - tmin) * 64.0f, -2.0f), 100.0f);
        ie  = (int)floorf(fe) - 1;
        ixb = (int)ceilf(fx_) + 1;
    } else {
        ie  = 1 << 30;
        ixb = -1;
    }
    int istart, iend;
    asm("redux.sync.min.s32 %0, %1, 0xffffffff;" : "=r"(istart) : "r"(ie));
    asm("redux.sync.max.s32 %0, %1, 0xffffffff;" : "=r"(iend)   : "r"(ixb));
    istart = max(istart, 0);
    iend   = min(iend, nsteps - 1);

    float rgbx = 0.f, rgby = 0.f, rgbz = 0.f, alpha = 0.f;
    const uint4* __restrict__ T = g_tpair + (lane << 12);

    #pragma unroll 1
    for (int i = istart; i <= iend; i++) {
        float t  = fmaf((float)i, DTSTEP, tmin);
        float y0 = fmaf(t, b0, a0);
        float y1 = fmaf(t, b1, a1);
        float y2 = fmaf(t, b2, a2);

        float sx = 0.f, sy = 0.f, sz = 0.f, sw = 0.f;
        if (fabsf(y0) <= 1.0f && fabsf(y1) <= 1.0f && fabsf(y2) <= 1.0f) {
            // component 0 -> z index, 1 -> y, 2 -> x ; g in [0,15] when inside
            float gz = (y0 + 1.0f) * 7.5f;
            float gy = (y1 + 1.0f) * 7.5f;
            float gx = (y2 + 1.0f) * 7.5f;
            int iz = min((int)gz, 14);
            int iy = min((int)gy, 14);
            int ixx = min((int)gx, 14);
            float fz = gz - (float)iz;
            float fy = gy - (float)iy;
            float fx = gx - (float)ixx;

            int base = iz * 256 + iy * 16 + ixx;
            uint4 q00 = __ldg(T + base);            // (iz,  iy)
            uint4 q01 = __ldg(T + base + 16);       // (iz,  iy+1)
            uint4 q10 = __ldg(T + base + 256);      // (iz+1,iy)
            uint4 q11 = __ldg(T + base + 272);      // (iz+1,iy+1)

            __half2 fx2 = __float2half2_rn(fx);
            __half2 fy2 = __float2half2_rn(fy);
            __half2 fz2 = __float2half2_rn(fz);

            __half2 rg00, ba00, rg01, ba01, rg10, ba10, rg11, ba11;
            xlerp_h2(q00, fx2, rg00, ba00);
            xlerp_h2(q01, fx2, rg01, ba01);
            xlerp_h2(q10, fx2, rg10, ba10);
            xlerp_h2(q11, fx2, rg11, ba11);

            __half2 rg0 = __hfma2(fy2, __hsub2(rg01, rg00), rg00);
            __half2 ba0 = __hfma2(fy2, __hsub2(ba01, ba00), ba00);
            __half2 rg1 = __hfma2(fy2, __hsub2(rg11, rg10), rg10);
            __half2 ba1 = __hfma2(fy2, __hsub2(ba11, ba10), ba10);

            __half2 rg = __hfma2(fz2, __hsub2(rg1, rg0), rg0);
            __half2 ba = __hfma2(fz2, __hsub2(ba1, ba0), ba0);

            float2 rgf = __half22float2(rg);
            float2 baf = __half22float2(ba);
            sx = rgf.x; sy = rgf.y; sz = baf.x; sw = baf.y;
        }

        // Warp-sum of alpha channel (butterfly; fp32 REDUX not on sm_103)
        #pragma unroll
        for (int off = 16; off; off >>= 1)
            sw += __shfl_xor_sync(0xffffffffu, sw, off);

        float na = fminf(fmaf(sw, DTSTEP, alpha), 1.0f);
        float contrib = na - alpha;         // warp-uniform
        rgbx = fmaf(sx, contrib, rgbx);     // per-lane partial; reduced at the end
        rgby = fmaf(sy, contrib, rgby);
        rgbz = fmaf(sz, contrib, rgbz);
        alpha = na;
        if (alpha >= 1.0f) break;           // saturated: all later contribs 0
    }

    // Final rgb reduction across the warp
    #pragma unroll
    for (int off = 16; off; off >>= 1) {
        rgbx += __shfl_xor_sync(0xffffffffu, rgbx, off);
        rgby += __shfl_xor_sync(0xffffffffu, rgby, off);
        rgbz += __shfl_xor_sync(0xffffffffu, rgbz, off);
    }

    if (lane == 0) {
        // out layout: rayrgb [1,3,H,W] | rayalpha [1,1,H,W] | rayrgba [1,4,H,W]
        out[0 * R_TOT + ray] = rgbx;
        out[1 * R_TOT + ray] = rgby;
        out[2 * R_TOT + ray] = rgbz;
        out[3 * R_TOT + ray] = alpha;
        out[4 * R_TOT + ray] = rgbx;
        out[5 * R_TOT + ray] = rgby;
        out[6 * R_TOT + ray] = rgbz;
        out[7 * R_TOT + ray] = alpha;
    }
}

extern "C" void kernel_launch(void* const* d_in, const int* in_sizes, int n_in,
                              void* d_out, int out_size) {
    const float* raypos    = (const float*)d_in[0];
    const float* raydir    = (const float*)d_in[1];
    const float* tminmax   = (const float*)d_in[2];
    const float* primpos   = (const float*)d_in[3];
    const float* primrot   = (const float*)d_in[4];
    const float* primscale = (const float*)d_in[5];
    const float* tmpl      = (const float*)d_in[6];
    float* out = (float*)d_out;

    pack_tmpl_kernel<<<(KPRIM * 4096 + 255) / 256, 256>>>(tmpl);

    int threads = R_TOT * 32;
    march_kernel<<<threads / 256, 256>>>(raypos, raydir, tminmax,
                                         primpos, primrot, primscale, out);
}

// round 12
// speedup vs baseline: 1.1059x; 1.0036x over previous
#include <cuda_runtime.h>
#include <cuda_fp16.h>

#define R_TOT   16384      // H*W rays
#define KPRIM   32
#define NSTEPS  64
#define DTSTEP  (1.0f/64.0f)
#define FXSCALE 1048576.0f         // 2^20 fixed-point scale for alpha redux
#define FXINV   (1.0f/1048576.0f)

// Packed template: per (k,z,y,x): {h2(r,g)@x, h2(b,a)@x, h2(r,g)@x+1, h2(b,a)@x+1} = 16B
__device__ uint4 g_tpair[KPRIM * 4096];   // 2 MB, L2-resident

// --- Prologue: pack template [K,4,16,16,16] fp32 -> channel-pair half2s ---
__global__ void pack_tmpl_kernel(const float* __restrict__ tmpl) {
    int idx = blockIdx.x * blockDim.x + threadIdx.x;
    if (idx >= KPRIM * 4096) return;
    int k = idx >> 12;
    int v = idx & 4095;            // z*256 + y*16 + x
    int x = v & 15;
    int x1 = (x < 15) ? 1 : 0;     // clamp x+1 (offset)
    const float* b = tmpl + (size_t)k * 4 * 4096;
    int p0 = v, p1 = v + x1;
    __half2 rg0 = __floats2half2_rn(b[p0],          b[4096 + p0]);
    __half2 ba0 = __floats2half2_rn(b[8192 + p0],   b[12288 + p0]);
    __half2 rg1 = __floats2half2_rn(b[p1],          b[4096 + p1]);
    __half2 ba1 = __floats2half2_rn(b[8192 + p1],   b[12288 + p1]);
    uint4 q;
    q.x = *(unsigned int*)&rg0;
    q.y = *(unsigned int*)&ba0;
    q.z = *(unsigned int*)&rg1;
    q.w = *(unsigned int*)&ba1;
    g_tpair[idx] = q;
}

__device__ __forceinline__ void xlerp_h2(uint4 q, __half2 fx2, __half2& rg, __half2& ba) {
    __half2 rg0 = *(__half2*)&q.x;
    __half2 ba0 = *(__half2*)&q.y;
    __half2 rg1 = *(__half2*)&q.z;
    __half2 ba1 = *(__half2*)&q.w;
    rg = __hfma2(fx2, __hsub2(rg1, rg0), rg0);
    ba = __hfma2(fx2, __hsub2(ba1, ba0), ba0);
}

// --- Main march: one warp per ray, one lane per primitive, half2 lerp tree ---
__global__ void __launch_bounds__(64) march_kernel(
    const float* __restrict__ raypos,
    const float* __restrict__ raydir,
    const float* __restrict__ tminmax,
    const float* __restrict__ primpos,
    const float* __restrict__ primrot,
    const float* __restrict__ primscale,
    float* __restrict__ out)
{
    int gtid = blockIdx.x * blockDim.x + threadIdx.x;
    int ray  = gtid >> 5;
    int lane = threadIdx.x & 31;
    if (ray >= R_TOT) return;

    float rpx = raypos[ray * 3 + 0];
    float rpy = raypos[ray * 3 + 1];
    float rpz = raypos[ray * 3 + 2];
    float rdx = raydir[ray * 3 + 0];
    float rdy = raydir[ray * 3 + 1];
    float rdz = raydir[ray * 3 + 2];
    float tmin = tminmax[ray * 2 + 0];
    float tmax = tminmax[ray * 2 + 1];

    // Affine transform coefficients: y_c(t) = a_c + t * b_c  (per-lane prim)
    float a0, a1, a2, b0, b1, b2;
    {
        float ppx = primpos[lane * 3 + 0];
        float ppy = primpos[lane * 3 + 1];
        float ppz = primpos[lane * 3 + 2];
        float r00 = primrot[lane * 9 + 0], r01 = primrot[lane * 9 + 1], r02 = primrot[lane * 9 + 2];
        float r10 = primrot[lane * 9 + 3], r11 = primrot[lane * 9 + 4], r12 = primrot[lane * 9 + 5];
        float r20 = primrot[lane * 9 + 6], r21 = primrot[lane * 9 + 7], r22 = primrot[lane * 9 + 8];
        float s0 = primscale[lane * 3 + 0];
        float s1 = primscale[lane * 3 + 1];
        float s2 = primscale[lane * 3 + 2];
        float dx = rpx - ppx, dy = rpy - ppy, dz = rpz - ppz;
        a0 = (r00 * dx + r01 * dy + r02 * dz) * s0;
        a1 = (r10 * dx + r11 * dy + r12 * dz) * s1;
        a2 = (r20 * dx + r21 * dy + r22 * dz) * s2;
        b0 = (r00 * rdx + r01 * rdy + r02 * rdz) * s0;
        b1 = (r10 * rdx + r11 * rdy + r12 * rdz) * s1;
        b2 = (r20 * rdx + r21 * rdy + r22 * rdz) * s2;
    }

    // Steps with t = tmin + i*DT < tmax
    int nsteps = (int)ceilf((tmax - tmin) * 64.0f);
    nsteps = min(nsteps, NSTEPS);

    // Per-lane slab interval [te, tx]: |a_c + t b_c| <= 1 for all c
    float te = -1e30f, tx = 1e30f;
    bool nonempty = true;
    {
        #define SLAB(A, B)                                                   \
        {                                                                    \
            if ((B) != 0.0f) {                                               \
                float u = (-1.0f - (A)) / (B);                               \
                float v = ( 1.0f - (A)) / (B);                               \
                te = fmaxf(te, fminf(u, v));                                 \
                tx = fminf(tx, fmaxf(u, v));                                 \
            } else if (fabsf(A) > 1.0f) {                                    \
                nonempty = false;                                            \
            }                                                                \
        }
        SLAB(a0, b0) SLAB(a1, b1) SLAB(a2, b2)
        #undef SLAB
        if (te > tx) nonempty = false;
    }

    // Step-index bounds (widened 1 step for rounding safety)
    int ie, ixb;
    if (nonempty) {
        float fe  = fminf(fmaxf((te - tmin) * 64.0f, -2.0f), 100.0f);
        float fx_ = fminf(fmaxf((tx - tmin) * 64.0f, -2.0f), 100.0f);
        ie  = (int)floorf(fe) - 1;
        ixb = (int)ceilf(fx_) + 1;
    } else {
        ie  = 1 << 30;
        ixb = -1;
    }
    int istart, iend;
    asm("redux.sync.min.s32 %0, %1, 0xffffffff;" : "=r"(istart) : "r"(ie));
    asm("redux.sync.max.s32 %0, %1, 0xffffffff;" : "=r"(iend)   : "r"(ixb));
    istart = max(istart, 0);
    iend   = min(iend, nsteps - 1);

    float rgbx = 0.f, rgby = 0.f, rgbz = 0.f, alpha = 0.f;
    const uint4* __restrict__ T = g_tpair + (lane << 12);

    #pragma unroll 1
    for (int i = istart; i <= iend; i++) {
        float t  = fmaf((float)i, DTSTEP, tmin);
        float y0 = fmaf(t, b0, a0);
        float y1 = fmaf(t, b1, a1);
        float y2 = fmaf(t, b2, a2);

        float sx = 0.f, sy = 0.f, sz = 0.f, sw = 0.f;
        if (fabsf(y0) <= 1.0f && fabsf(y1) <= 1.0f && fabsf(y2) <= 1.0f) {
            // component 0 -> z index, 1 -> y, 2 -> x ; g in [0,15] when inside
            float gz = (y0 + 1.0f) * 7.5f;
            float gy = (y1 + 1.0f) * 7.5f;
            float gx = (y2 + 1.0f) * 7.5f;
            int iz = min((int)gz, 14);
            int iy = min((int)gy, 14);
            int ixx = min((int)gx, 14);
            float fz = gz - (float)iz;
            float fy = gy - (float)iy;
            float fx = gx - (float)ixx;

            int base = iz * 256 + iy * 16 + ixx;
            uint4 q00 = __ldg(T + base);            // (iz,  iy)
            uint4 q01 = __ldg(T + base + 16);       // (iz,  iy+1)
            uint4 q10 = __ldg(T + base + 256);      // (iz+1,iy)
            uint4 q11 = __ldg(T + base + 272);      // (iz+1,iy+1)

            __half2 fx2 = __float2half2_rn(fx);
            __half2 fy2 = __float2half2_rn(fy);
            __half2 fz2 = __float2half2_rn(fz);

            __half2 rg00, ba00, rg01, ba01, rg10, ba10, rg11, ba11;
            xlerp_h2(q00, fx2, rg00, ba00);
            xlerp_h2(q01, fx2, rg01, ba01);
            xlerp_h2(q10, fx2, rg10, ba10);
            xlerp_h2(q11, fx2, rg11, ba11);

            __half2 rg0 = __hfma2(fy2, __hsub2(rg01, rg00), rg00);
            __half2 ba0 = __hfma2(fy2, __hsub2(ba01, ba00), ba00);
            __half2 rg1 = __hfma2(fy2, __hsub2(rg11, rg10), rg10);
            __half2 ba1 = __hfma2(fy2, __hsub2(ba11, ba10), ba10);

            __half2 rg = __hfma2(fz2, __hsub2(rg1, rg0), rg0);
            __half2 ba = __hfma2(fz2, __hsub2(ba1, ba0), ba0);

            float2 rgf = __half22float2(rg);
            float2 baf = __half22float2(ba);
            sx = rgf.x; sy = rgf.y; sz = baf.x; sw = baf.y;
        }

        // Warp-sum of alpha channel: fixed-point integer REDUX (1 op vs 5-SHFL chain)
        int isw = __float2int_rn(sw * FXSCALE);
        asm("redux.sync.add.s32 %0, %1, 0xffffffff;" : "=r"(isw) : "r"(isw));
        float swsum = (float)isw * FXINV;

        float na = fminf(fmaf(swsum, DTSTEP, alpha), 1.0f);
        float contrib = na - alpha;         // warp-uniform
        rgbx = fmaf(sx, contrib, rgbx);     // per-lane partial; reduced at the end
        rgby = fmaf(sy, contrib, rgby);
        rgbz = fmaf(sz, contrib, rgbz);
        alpha = na;
        if (alpha >= 1.0f) break;           // saturated: all later contribs 0
    }

    // Final rgb reduction across the warp
    #pragma unroll
    for (int off = 16; off; off >>= 1) {
        rgbx += __shfl_xor_sync(0xffffffffu, rgbx, off);
        rgby += __shfl_xor_sync(0xffffffffu, rgby, off);
        rgbz += __shfl_xor_sync(0xffffffffu, rgbz, off);
    }

    // Spread the 8 stores over lanes 0-7
    // out layout: rayrgb [1,3,H,W] | rayalpha [1,1,H,W] | rayrgba [1,4,H,W]
    float vals[8] = {rgbx, rgby, rgbz, alpha, rgbx, rgby, rgbz, alpha};
    if (lane < 8)
        out[lane * R_TOT + ray] = vals[lane];
}

extern "C" void kernel_launch(void* const* d_in, const int* in_sizes, int n_in,
                              void* d_out, int out_size) {
    const float* raypos    = (const float*)d_in[0];
    const float* raydir    = (const float*)d_in[1];
    const float* tminmax   = (const float*)d_in[2];
    const float* primpos   = (const float*)d_in[3];
    const float* primrot   = (const float*)d_in[4];
    const float* primscale = (const float*)d_in[5];
    const float* tmpl      = (const float*)d_in[6];
    float* out = (float*)d_out;

    pack_tmpl_kernel<<<(KPRIM * 4096 + 255) / 256, 256>>>(tmpl);

    int threads = R_TOT * 32;
    march_kernel<<<threads / 64, 64>>>(raypos, raydir, tminmax,
                                       primpos, primrot, primscale, out);
}